// round 17
// baseline (speedup 1.0000x reference)
#include <cuda_runtime.h>
#include <cuda_fp16.h>
#include <cstdint>

#define NB 8
#define NC 256
#define NM 128
#define NPIX 16384
#define EPSV 1e-6f
#define NBLK 37   // blocks per batch -> 296 = one perfect wave @ 2 CTA/SM

// ---------------- scratch ----------------
__device__ __half g_QhT[(size_t)NB*NPIX*NM];  // Qn transposed: [b][n][m]
__device__ __half g_Kh [(size_t)NB*NM*NPIX];  // Kn: [b][m][n]
__device__ __half g_xh [(size_t)NB*NC*NPIX];  // x in fp16: [b][c][n]
__device__ float  g_Ksum[NB*NM];
__device__ float  g_xsum[NB*NC];
__device__ float  g_vsum[NB*NC];
__device__ float  g_kxT[(size_t)NB*NC*NM];    // [b][xc][m] (fp32 atomics)
__device__ __half g_matTh[(size_t)NB*NC*NM];  // [b][c][m]

__device__ __forceinline__ unsigned smem_u32(const void* p){
    unsigned a; asm("{ .reg .u64 t; cvta.to.shared.u64 t, %1; cvt.u32.u64 %0, t; }":"=r"(a):"l"(p)); return a;
}
__device__ __forceinline__ void mma_tf32(float* d, const unsigned* a, const unsigned* b){
    asm volatile("mma.sync.aligned.m16n8k8.row.col.f32.tf32.tf32.f32 "
        "{%0,%1,%2,%3}, {%4,%5,%6,%7}, {%8,%9}, {%0,%1,%2,%3};"
        : "+f"(d[0]), "+f"(d[1]), "+f"(d[2]), "+f"(d[3])
        : "r"(a[0]), "r"(a[1]), "r"(a[2]), "r"(a[3]), "r"(b[0]), "r"(b[1]));
}
__device__ __forceinline__ void mma_f16(float* d, const unsigned* a, const unsigned* b){
    asm volatile("mma.sync.aligned.m16n8k16.row.col.f32.f16.f16.f32 "
        "{%0,%1,%2,%3}, {%4,%5,%6,%7}, {%8,%9}, {%0,%1,%2,%3};"
        : "+f"(d[0]), "+f"(d[1]), "+f"(d[2]), "+f"(d[3])
        : "r"(a[0]), "r"(a[1]), "r"(a[2]), "r"(a[3]), "r"(b[0]), "r"(b[1]));
}
__device__ __forceinline__ void cpa(unsigned d, const void* s){
    asm volatile("cp.async.cg.shared.global [%0], [%1], 16;"::"r"(d),"l"(s));
}
#define CPA_COMMIT() asm volatile("cp.async.commit_group;" ::: "memory")
#define CPA_WAIT1()  asm volatile("cp.async.wait_group 1;" ::: "memory")
#define CPA_WAIT0()  asm volatile("cp.async.wait_group 0;" ::: "memory")

// -------- fp32 fills (qk / matfix) --------
template<int NT>
__device__ __forceinline__ void fillT36(unsigned dst, const float* src, size_t stride, int tid){
    #pragma unroll
    for (int s = 0; s < 1024/NT; s++){
        int idx = tid + NT*s;
        int row = idx >> 3, kq = idx & 7;
        cpa(dst + (unsigned)(row*36 + 4*kq)*4u, src + (size_t)row*stride + 4*kq);
    }
}
template<int NT>
__device__ __forceinline__ void fillKN(unsigned dst, const float* src, size_t stride, int tid){
    #pragma unroll
    for (int s = 0; s < 1024/NT; s++){
        int idx = tid + NT*s;
        int k = idx >> 5, nq = idx & 31;
        cpa(dst + (unsigned)(k*136 + 4*nq)*4u, src + (size_t)k*stride + 4*nq);
    }
}
// -------- fp16 fills: [row 0..127][k 0..31] halves, stride 40 (80 B/row) ------
__device__ __forceinline__ void fillH40(unsigned dst, const __half* src, size_t stride, int tid){
    #pragma unroll
    for (int s = 0; s < 4; s++){
        int idx = tid + 128*s;
        int row = idx >> 2, ck = idx & 3;
        cpa(dst + (unsigned)(row*80 + ck*16), src + (size_t)row*stride + ck*8);
    }
}
// resident matTh: [128][128] halves, stride 136 (272 B/row)
__device__ __forceinline__ void fillH136(unsigned dst, const __half* src, size_t stride, int tid){
    #pragma unroll
    for (int s = 0; s < 16; s++){
        int idx = tid + 128*s;
        int row = idx >> 4, ck = idx & 15;
        cpa(dst + (unsigned)(row*272 + ck*16), src + (size_t)row*stride + ck*8);
    }
}

// -------- tf32 64x64 warp tile (qk) --------
template<int AS, int BKN>
__device__ __forceinline__ void mma_stage64(const float* As, const float* Bs,
        float acc[4][8][4], int wm, int wn, int lane){
    const int lq = lane & 3, lr = lane >> 2;
    #pragma unroll
    for (int kk = 0; kk < 4; kk++){
        const int k0 = kk*8 + lq;
        unsigned a[4][4], bf[8][2];
        #pragma unroll
        for (int i = 0; i < 4; i++){
            int mr = wm*64 + i*16 + lr;
            a[i][0] = __float_as_uint(As[mr*AS + k0]);
            a[i][1] = __float_as_uint(As[(mr+8)*AS + k0]);
            a[i][2] = __float_as_uint(As[mr*AS + k0 + 4]);
            a[i][3] = __float_as_uint(As[(mr+8)*AS + k0 + 4]);
        }
        #pragma unroll
        for (int j = 0; j < 8; j++){
            int nc = wn*64 + j*8 + lr;
            if (BKN == 0){
                bf[j][0] = __float_as_uint(Bs[nc*36 + k0]);
                bf[j][1] = __float_as_uint(Bs[nc*36 + k0 + 4]);
            } else {
                bf[j][0] = __float_as_uint(Bs[k0*136 + nc]);
                bf[j][1] = __float_as_uint(Bs[(k0+4)*136 + nc]);
            }
        }
        #pragma unroll
        for (int i = 0; i < 4; i++)
            #pragma unroll
            for (int j = 0; j < 8; j++)
                mma_tf32(acc[i][j], a[i], bf[j]);
    }
}

// -------- fp16 64x64 warp tile: both tiles [row][k], 2 ksteps of m16n8k16 ----
template<int ASA, int ASB>
__device__ __forceinline__ void mma_stage64h(const __half* As, const __half* Bs,
        float acc[4][8][4], int wm, int wn, int lane, int kA, int kB){
    const int lq = lane & 3, lr = lane >> 2;
    #pragma unroll
    for (int kk = 0; kk < 2; kk++){
        const int ka = kA + kk*16 + 2*lq;
        const int kb = kB + kk*16 + 2*lq;
        unsigned a[4][4], bf[8][2];
        #pragma unroll
        for (int i = 0; i < 4; i++){
            int mr = wm*64 + i*16 + lr;
            a[i][0] = *reinterpret_cast<const unsigned*>(&As[mr*ASA + ka]);
            a[i][1] = *reinterpret_cast<const unsigned*>(&As[(mr+8)*ASA + ka]);
            a[i][2] = *reinterpret_cast<const unsigned*>(&As[mr*ASA + ka + 8]);
            a[i][3] = *reinterpret_cast<const unsigned*>(&As[(mr+8)*ASA + ka + 8]);
        }
        #pragma unroll
        for (int j = 0; j < 8; j++){
            int nc = wn*64 + j*8 + lr;
            bf[j][0] = *reinterpret_cast<const unsigned*>(&Bs[nc*ASB + kb]);
            bf[j][1] = *reinterpret_cast<const unsigned*>(&Bs[nc*ASB + kb + 8]);
        }
        #pragma unroll
        for (int i = 0; i < 4; i++)
            #pragma unroll
            for (int j = 0; j < 8; j++)
                mma_f16(acc[i][j], a[i], bf[j]);
    }
}

// -------- tf32 32x64 tile (matfix, 256 thr) --------
template<int AS, int BKN>
__device__ __forceinline__ void mma_stage(const float* As, const float* Bs,
        float acc[2][8][4], int wm, int wn, int lane){
    const int lq = lane & 3, lr = lane >> 2;
    #pragma unroll
    for (int kk = 0; kk < 4; kk++){
        const int k0 = kk*8 + lq;
        unsigned a[2][4], bf[8][2];
        #pragma unroll
        for (int i = 0; i < 2; i++){
            int mr = wm*32 + i*16 + lr;
            a[i][0] = __float_as_uint(As[mr*AS + k0]);
            a[i][1] = __float_as_uint(As[(mr+8)*AS + k0]);
            a[i][2] = __float_as_uint(As[mr*AS + k0 + 4]);
            a[i][3] = __float_as_uint(As[(mr+8)*AS + k0 + 4]);
        }
        #pragma unroll
        for (int j = 0; j < 8; j++){
            int nc = wn*64 + j*8 + lr;
            if (BKN == 0){
                bf[j][0] = __float_as_uint(Bs[nc*36 + k0]);
                bf[j][1] = __float_as_uint(Bs[nc*36 + k0 + 4]);
            } else {
                bf[j][0] = __float_as_uint(Bs[k0*136 + nc]);
                bf[j][1] = __float_as_uint(Bs[(k0+4)*136 + nc]);
            }
        }
        #pragma unroll
        for (int i = 0; i < 2; i++)
            #pragma unroll
            for (int j = 0; j < 8; j++)
                mma_tf32(acc[i][j], a[i], bf[j]);
    }
}

// zero the atomic accumulators (Ksum/xsum; kxT zeroed in gemm_qk)
__global__ void zero_small(){
    const int total = NB*NM + NB*NC;
    for (int i = threadIdx.x; i < total; i += blockDim.x){
        if (i < NB*NM) g_Ksum[i] = 0.f;
        else g_xsum[i - NB*NM] = 0.f;
    }
}

// ========== GEMM1: Q,K projections (tf32); writes QhT/Kh/xh fp16 ==========
// grid (2 mt, 128 nblk, 8 b), 128 thr; 8 stages of K=32
#define QSTG 8960
#define QAUX (2*QSTG)
#define QSMEM ((QAUX + 384)*4)
__global__ __launch_bounds__(128, 2) void gemm_qk(
    const float* __restrict__ x,
    const float* __restrict__ Wq, const float* __restrict__ bq,
    const float* __restrict__ Wk, const float* __restrict__ bk)
{
    extern __shared__ float smf[];
    const unsigned sb = smem_u32(smf);
    const int mt = blockIdx.x, nblk = blockIdx.y, b = blockIdx.z;
    const int tid = threadIdx.x, lane = tid & 31, wid = tid >> 5;
    const int wm = wid & 1, wn = wid >> 1;
    const int n0 = nblk * 128;

    const float* W     = mt ? Wk : Wq;
    const float* biasp = mt ? bk : bq;
    const float* xb = x + (size_t)b*NC*NPIX + n0;

    float* xs   = smf + QAUX;
    float* sred = xs + 256;
    if (mt == 0){ xs[tid] = 0.f; xs[tid + 128] = 0.f; }

    float acc[4][8][4] = {};
    fillT36<128>(sb, W, NC, tid);
    fillKN<128>(sb + 4608*4, xb, NPIX, tid);
    CPA_COMMIT();

    {   // fold kxT zeroing (overlaps first fills)
        const int gid = ((blockIdx.z*gridDim.y + blockIdx.y)*gridDim.x
                         + blockIdx.x)*128 + tid;
        if (gid < NB*NC*NM) g_kxT[gid] = 0.f;
    }

    for (int it = 0; it < 8; ++it){
        const int cur = it & 1;
        if (it + 1 < 8){
            const int nx = (it+1) & 1, kt = (it+1)*32;
            fillT36<128>(sb + (nx*QSTG)*4,        W + kt, NC, tid);
            fillKN<128>(sb + (nx*QSTG + 4608)*4,  xb + (size_t)kt*NPIX, NPIX, tid);
            CPA_COMMIT(); CPA_WAIT1();
        } else CPA_WAIT0();
        __syncthreads();
        if (mt == 0){   // xsum + xh conversion from resident x tile
            const float* Bc = smf + cur*QSTG + 4608;
            int k = tid >> 2, pc = (tid & 3) * 32;
            __half2* dx = reinterpret_cast<__half2*>(
                g_xh + ((size_t)b*NC + it*32 + k)*NPIX + n0 + pc);
            float s = 0.f;
            #pragma unroll
            for (int p = 0; p < 16; p++){
                float v0 = Bc[k*136 + pc + 2*p], v1 = Bc[k*136 + pc + 2*p + 1];
                s += v0 + v1;
                dx[p] = __floats2half2_rn(v0, v1);
            }
            s += __shfl_down_sync(0xffffffff, s, 2);
            s += __shfl_down_sync(0xffffffff, s, 1);
            if ((tid & 3) == 0) xs[it*32 + k] += s;
        }
        mma_stage64<36,1>(smf + cur*QSTG, smf + cur*QSTG + 4608, acc, wm, wn, lane);
        __syncthreads();
    }

    // ---- epilogue: bias -> Tile; norms; fp16 stores; Ksum/xsum ----
    float* Tile = smf;
    const int lq = lane & 3, lr = lane >> 2;
    #pragma unroll
    for (int i = 0; i < 4; i++){
        int r = wm*64 + i*16 + lr;
        float bA = biasp[r], bB = biasp[r+8];
        #pragma unroll
        for (int j = 0; j < 8; j++){
            int c = wn*64 + j*8 + 2*lq;
            Tile[r*129 + c]       = acc[i][j][0] + bA;
            Tile[r*129 + c + 1]   = acc[i][j][1] + bA;
            Tile[(r+8)*129 + c]   = acc[i][j][2] + bB;
            Tile[(r+8)*129 + c+1] = acc[i][j][3] + bB;
        }
    }
    __syncthreads();
    {
        float s = 0.f;
        #pragma unroll 16
        for (int r = 0; r < 128; r++){ float v = Tile[r*129 + tid]; s = fmaf(v, v, s); }
        sred[tid] = rsqrtf(s);
    }
    __syncthreads();
    if (mt == 0){
        // Qn transposed fp16: thread tid owns pixel n0+tid, writes 128 m values
        const float sc = sred[tid];
        __half2* dq = reinterpret_cast<__half2*>(
            g_QhT + ((size_t)b*NPIX + n0 + tid)*NM);
        #pragma unroll 8
        for (int m2 = 0; m2 < 64; m2++)
            dq[m2] = __floats2half2_rn(Tile[(2*m2)*129 + tid]*sc,
                                       Tile[(2*m2+1)*129 + tid]*sc);
        atomicAdd(&g_xsum[b*NC + tid], xs[tid]);
        atomicAdd(&g_xsum[b*NC + 128 + tid], xs[128 + tid]);
    } else {
        // Kn fp16 [m][n]
        const int col2 = (tid & 63)*2, rg = tid >> 6;
        float s0 = sred[col2], s1 = sred[col2+1];
        __half* Kp = g_Kh + (size_t)b*NM*NPIX + n0 + col2;
        #pragma unroll 8
        for (int rr = 0; rr < 64; rr++){
            int r = rg*64 + rr;
            *reinterpret_cast<__half2*>(Kp + (size_t)r*NPIX) =
                __floats2half2_rn(Tile[r*129 + col2]*s0, Tile[r*129 + col2+1]*s1);
        }
        float s = 0.f;
        #pragma unroll 16
        for (int c = 0; c < 128; c++) s = fmaf(Tile[tid*129 + c], sred[c], s);
        atomicAdd(&g_Ksum[b*NM + tid], s);
    }
}

// ========== GEMM2: kxT += xh @ Kh^T (fp16 MMA); perfect wave ==========
#define KSTGH 20480             // A(10240)+B(10240) bytes
#define KSMEM (2*KSTGH)
__global__ __launch_bounds__(128, 2) void gemm_km(){
    extern __shared__ __align__(16) char smc[];
    const unsigned sb = smem_u32(smc);
    const __half* smh = reinterpret_cast<const __half*>(smc);
    const int bi = blockIdx.x, b = blockIdx.y;
    const int tid = threadIdx.x, lane = tid & 31, wid = tid >> 5;
    const int wm = wid & 1, wn = wid >> 1;
    const int u0 = (bi * 1024) / NBLK, u1 = ((bi + 1) * 1024) / NBLK;

    const __half* xbase = g_xh + (size_t)b*NC*NPIX;
    const __half* Kbase = g_Kh + (size_t)b*NM*NPIX;

    float acc[4][8][4] = {};
    {
        int ch = u0 >> 9, st = u0 & 511;
        fillH40(sb,         xbase + (size_t)ch*128*NPIX + st*32, NPIX, tid);
        fillH40(sb + 10240, Kbase + st*32, NPIX, tid);
        CPA_COMMIT();
    }
    for (int u = u0; u < u1; ++u){
        const int cur = (u - u0) & 1;
        if (u + 1 < u1){
            const int nx = (u - u0 + 1) & 1;
            int ch = (u+1) >> 9, st = (u+1) & 511;
            fillH40(sb + nx*KSTGH,         xbase + (size_t)ch*128*NPIX + st*32, NPIX, tid);
            fillH40(sb + nx*KSTGH + 10240, Kbase + st*32, NPIX, tid);
            CPA_COMMIT(); CPA_WAIT1();
        } else CPA_WAIT0();
        __syncthreads();
        mma_stage64h<40,40>(smh + cur*(KSTGH/2), smh + cur*(KSTGH/2) + 5120,
                            acc, wm, wn, lane, 0, 0);
        __syncthreads();

        const bool flush = (u + 1 == u1) || ((u >> 9) != ((u + 1) >> 9));
        if (flush){
            const int ch = u >> 9;
            const int lq = lane & 3, lr = lane >> 2;
            #pragma unroll
            for (int i = 0; i < 4; i++){
                int r = wm*64 + i*16 + lr;
                float* m0 = g_kxT + ((size_t)b*NC + ch*128 + r)*NM;
                float* m1 = m0 + 8*NM;
                #pragma unroll
                for (int j = 0; j < 8; j++){
                    int c = wn*64 + j*8 + 2*lq;
                    atomicAdd(&m0[c],   acc[i][j][0]);
                    atomicAdd(&m0[c+1], acc[i][j][1]);
                    atomicAdd(&m1[c],   acc[i][j][2]);
                    atomicAdd(&m1[c+1], acc[i][j][3]);
                }
            }
            #pragma unroll
            for (int i = 0; i < 4; i++)
                #pragma unroll
                for (int j = 0; j < 8; j++)
                    #pragma unroll
                    for (int q = 0; q < 4; q++) acc[i][j][q] = 0.f;
        }
    }
}

// ========== matfix: matTh = fp16(Wv@kxT^T + bv x Ksum); vsum direct ==========
// grid (2 ch, 8 b), 256 thr; K=256 -> 8 stages (tf32)
#define MSTG 8960
#define MAUX (2*MSTG)
#define MSMEM ((MAUX + 640)*4)
__global__ __launch_bounds__(256, 2) void matfix(
    const float* __restrict__ Wv, const float* __restrict__ bv)
{
    extern __shared__ float smf[];
    const unsigned sb = smem_u32(smf);
    const int ch = blockIdx.x, b = blockIdx.y;
    const int tid = threadIdx.x, lane = tid & 31, wid = tid >> 5;
    const int wm = wid & 3, wn = wid >> 2;

    float* xs   = smf + MAUX;        // 256
    float* ksm  = xs + 256;          // 128
    float* dsum = ksm + 128;         // 256
    xs[tid] = g_xsum[b*NC + tid];
    if (tid < 128) ksm[tid] = g_Ksum[b*NM + tid];
    __syncthreads();

    const float* WA = Wv + (size_t)ch*128*NC;
    const float* KB = g_kxT + (size_t)b*NC*NM;

    const int dn = tid & 127, dh = tid >> 7;
    float vsp = 0.f;
    float acc[2][8][4] = {};

    fillT36<256>(sb, WA, NC, tid);
    fillKN<256>(sb + 4608*4, KB, NM, tid);
    CPA_COMMIT();
    for (int it = 0; it < 8; ++it){
        const int cur = it & 1;
        if (it + 1 < 8){
            const int nx = (it+1) & 1, kt = (it+1)*32;
            fillT36<256>(sb + (nx*MSTG)*4,       WA + kt, NC, tid);
            fillKN<256>(sb + (nx*MSTG + 4608)*4, KB + (size_t)kt*NM, NM, tid);
            CPA_COMMIT(); CPA_WAIT1();
        } else CPA_WAIT0();
        __syncthreads();
        {
            const float* Ac = smf + cur*MSTG;
            const int kt = it*32;
            #pragma unroll
            for (int p = 0; p < 16; p++){
                int k = dh*16 + p;
                vsp = fmaf(Ac[dn*36 + k], xs[kt + k], vsp);
            }
        }
        mma_stage<36,1>(smf + cur*MSTG, smf + cur*MSTG + 4608, acc, wm, wn, lane);
        __syncthreads();
    }

    dsum[dh*128 + dn] = vsp;
    __syncthreads();
    if (tid < 128)
        g_vsum[b*NC + ch*128 + tid] =
            dsum[tid] + dsum[128 + tid] + (float)NPIX * bv[ch*128 + tid];

    const int lq = lane & 3, lr = lane >> 2;
    #pragma unroll
    for (int i = 0; i < 2; i++){
        int r = wm*32 + i*16 + lr;
        float bv0 = bv[ch*128 + r], bv1 = bv[ch*128 + r + 8];
        __half* m0 = g_matTh + ((size_t)b*NC + ch*128 + r)*NM;
        __half* m1 = m0 + 8*NM;
        #pragma unroll
        for (int j = 0; j < 8; j++){
            int c = wn*64 + j*8 + 2*lq;
            *reinterpret_cast<__half2*>(&m0[c]) = __floats2half2_rn(
                acc[i][j][0] + bv0*ksm[c], acc[i][j][1] + bv0*ksm[c+1]);
            *reinterpret_cast<__half2*>(&m1[c]) = __floats2half2_rn(
                acc[i][j][2] + bv1*ksm[c], acc[i][j][3] + bv1*ksm[c+1]);
        }
    }
}

// ========== GEMM3: out[c][n] (fp16 MMA); resident matTh; perfect wave =========
#define GBH 34816                // resident matTh bytes (128*272)
#define OSTGH 10240              // B stage bytes
#define OAUXB (GBH + 2*OSTGH)    // 55296; aux floats after
#define OSMEM (OAUXB + 384*4)    // 56832
__global__ __launch_bounds__(128, 2) void gemm_out(
    const float* __restrict__ gamma, float* __restrict__ out)
{
    extern __shared__ __align__(16) char smc[];
    const unsigned sb = smem_u32(smc);
    const __half* smh = reinterpret_cast<const __half*>(smc);
    float* aux = reinterpret_cast<float*>(smc + OAUXB);
    const int bi = blockIdx.x, b = blockIdx.y;
    const int tid = threadIdx.x, lane = tid & 31, wid = tid >> 5;
    const int wm = wid & 1, wn = wid >> 1;
    const int u0 = (bi * 256) / NBLK, u1 = ((bi + 1) * 256) / NBLK;

    float* ks  = aux;        // 128
    float* svs = ks + 128;   // 128
    float* stl = svs + 128;  // 128
    ks[tid] = g_Ksum[b*NM + tid] + EPSV;

    const int lq = lane & 3, lr = lane >> 2;
    int cur_ch = -1;

    for (int u = u0; u < u1; ++u){
        const int ch = u >> 7, nt = u & 127;
        if (ch != cur_ch){
            __syncthreads();
            fillH136(sb, g_matTh + ((size_t)b*NC + ch*128)*NM, NM, tid);
            CPA_COMMIT();
            svs[tid] = g_vsum[b*NC + ch*128 + tid];
            cur_ch = ch;
        }
        const int n0 = nt * 128;
        const __half* Qb = g_QhT + ((size_t)b*NPIX + n0)*NM;

        float acc[4][8][4] = {};
        float ddv = 0.f;

        fillH40(sb + GBH, Qb, NM, tid);
        CPA_COMMIT();
        for (int it = 0; it < 4; ++it){
            const int cur = it & 1;
            if (it + 1 < 4){
                fillH40(sb + GBH + ((it+1)&1)*OSTGH, Qb + (it+1)*32, NM, tid);
                CPA_COMMIT(); CPA_WAIT1();
            } else CPA_WAIT0();
            __syncthreads();
            {   // fused tailor dot: thread tid owns pixel tid (B row tid)
                const __half* Bc = smh + (GBH + cur*OSTGH)/2;
                const int m0 = it*32;
                #pragma unroll
                for (int k = 0; k < 32; k++)
                    ddv = fmaf(__half2float(Bc[tid*40 + k]), ks[m0 + k], ddv);
            }
            mma_stage64h<136,40>(smh, smh + (GBH + cur*OSTGH)/2,
                                 acc, wm, wn, lane, it*32, 0);
            __syncthreads();
        }

        stl[tid] = gamma[0] / ((float)NPIX + ddv);
        __syncthreads();

        float* ob = out + ((size_t)b*NC + (size_t)cur_ch*128)*NPIX + n0;
        #pragma unroll
        for (int i = 0; i < 4; i++){
            int r = wm*64 + i*16 + lr;
            float v0 = svs[r], v1 = svs[r+8];
            #pragma unroll
            for (int j = 0; j < 8; j++){
                int c = wn*64 + j*8 + 2*lq;
                float t0 = stl[c], t1 = stl[c+1];
                *reinterpret_cast<float2*>(&ob[(size_t)r*NPIX + c]) =
                    make_float2(t0*(v0 + acc[i][j][0]), t1*(v0 + acc[i][j][1]));
                *reinterpret_cast<float2*>(&ob[(size_t)(r+8)*NPIX + c]) =
                    make_float2(t0*(v1 + acc[i][j][2]), t1*(v1 + acc[i][j][3]));
            }
        }
        __syncthreads();
    }
}

// ---------------- launch ----------------
extern "C" void kernel_launch(void* const* d_in, const int* in_sizes, int n_in,
                              void* d_out, int out_size)
{
    const float* x     = (const float*)d_in[0];
    const float* Wq    = (const float*)d_in[1];
    const float* bq    = (const float*)d_in[2];
    const float* Wk    = (const float*)d_in[3];
    const float* bk    = (const float*)d_in[4];
    const float* Wv    = (const float*)d_in[5];
    const float* bv    = (const float*)d_in[6];
    const float* gamma = (const float*)d_in[7];
    float* out = (float*)d_out;

    static bool attr_done = false;
    if (!attr_done){
        cudaFuncSetAttribute(gemm_qk,  cudaFuncAttributeMaxDynamicSharedMemorySize, QSMEM);
        cudaFuncSetAttribute(gemm_km,  cudaFuncAttributeMaxDynamicSharedMemorySize, KSMEM);
        cudaFuncSetAttribute(matfix,   cudaFuncAttributeMaxDynamicSharedMemorySize, MSMEM);
        cudaFuncSetAttribute(gemm_out, cudaFuncAttributeMaxDynamicSharedMemorySize, OSMEM);
        attr_done = true;
    }

    zero_small<<<1, 256>>>();
    gemm_qk<<<dim3(2, 128, NB), 128, QSMEM>>>(x, Wq, bq, Wk, bk);
    gemm_km<<<dim3(NBLK, NB), 128, KSMEM>>>();
    matfix<<<dim3(2, NB), 256, MSMEM>>>(Wv, bv);
    gemm_out<<<dim3(NBLK, NB), 128, OSMEM>>>(gamma, out);
}